// round 7
// baseline (speedup 1.0000x reference)
#include <cuda_runtime.h>
#include <cstdint>
#include <cooperative_groups.h>
#include <cooperative_groups/reduce.h>
namespace cg = cooperative_groups;

#define N_CODES 100000
#define CODE_DIM 256
#define HIDDEN 128
#define HEADS 4
#define N_SPEC 256

#define GRID 296               // 2 blocks/SM on 148 SMs, one wave
#define NW (GRID * 8)          // 2368 warps, ~42 rows each
#define DEPTH 8                // per-warp cp.async pipeline depth (rows)
#define L2E 1.4426950408889634f

// ---------------- scratch (device globals) ----------------------------------
__device__ __align__(16) float g_v[HEADS * CODE_DIM];   // W[h]@a2[h]
__device__ float g_c[HEADS];
__device__ __align__(16) float g_partB[GRID * HEADS * CODE_DIM];
__device__ float g_mb[GRID * HEADS];
__device__ float g_zb[GRID * HEADS];
__device__ __align__(16) float g_part2[16 * CODE_DIM];  // 4 quarters x 4 heads
__device__ __align__(16) float g_G[N_SPEC * HEADS * CODE_DIM]; // folded W@Wc (1MB)
__device__ float g_bc2[N_SPEC];                         // bc + b.Wc fold

// ---------------- f32x2 helpers (Blackwell packed fp32) ----------------------
__device__ __forceinline__ uint64_t fma2(uint64_t a, uint64_t b, uint64_t c) {
    uint64_t d;
    asm("fma.rn.f32x2 %0, %1, %2, %3;" : "=l"(d) : "l"(a), "l"(b), "l"(c));
    return d;
}
__device__ __forceinline__ uint64_t mul2(uint64_t a, uint64_t b) {
    uint64_t d;
    asm("mul.rn.f32x2 %0, %1, %2;" : "=l"(d) : "l"(a), "l"(b));
    return d;
}
__device__ __forceinline__ uint64_t pack2(float x) {
    uint64_t d;
    asm("mov.b64 %0, {%1, %1};" : "=l"(d) : "f"(x));
    return d;
}
__device__ __forceinline__ float2 unpack2(uint64_t p) {
    uint32_t lo, hi;
    asm("mov.b64 {%0, %1}, %2;" : "=r"(lo), "=r"(hi) : "l"(p));
    return make_float2(__uint_as_float(lo), __uint_as_float(hi));
}

// ---------------- cp.async helpers ------------------------------------------
__device__ __forceinline__ void cp_async16(void* smem, const void* gmem) {
    uint32_t s = (uint32_t)__cvta_generic_to_shared(smem);
    asm volatile("cp.async.cg.shared.global [%0], [%1], 16;\n" :: "r"(s), "l"(gmem));
}
__device__ __forceinline__ void cp_commit() {
    asm volatile("cp.async.commit_group;\n" ::: "memory");
}
template<int N> __device__ __forceinline__ void cp_wait() {
    asm volatile("cp.async.wait_group %0;\n" :: "n"(N) : "memory");
}

// ---------------- K1: prep (v projections + score constants) -----------------
// blocks 0,1 (512 thr): v[h][d] = W[h,d,:]·a2[h]
// block 2   (512 thr): c[h] = (p@W[h])·a1[h] + b[h]·(a1[h]+a2[h])
__global__ void __launch_bounds__(512) k_prep(const float* __restrict__ W,
                                              const float* __restrict__ a,
                                              const float* __restrict__ p,
                                              const float* __restrict__ bb) {
    int t = threadIdx.x;
    if (blockIdx.x < 2) {
        int idx = blockIdx.x * 512 + t;          // 0..1023 = (h,d)
        int h = idx >> 8;
        const float4* wr = (const float4*)(W + (size_t)idx * 128);
        const float4* a2 = (const float4*)(a + h * 256 + 128);
        float av = 0.f;
        #pragma unroll
        for (int q = 0; q < 32; q++) {
            float4 w = wr[q], x = a2[q];
            av += w.x * x.x + w.y * x.y + w.z * x.z + w.w * x.w;
        }
        g_v[idx] = av;
    } else {
        __shared__ float psh[256];
        __shared__ float red[512];
        if (t < 256) psh[t] = p[t];
        __syncthreads();
        int h = t >> 7, k = t & 127;
        const float* wp = W + (size_t)h * 256 * 128 + k;
        float ph = 0.f;
        #pragma unroll 8
        for (int d = 0; d < 256; d++) ph = fmaf(psh[d], wp[(size_t)d * 128], ph);
        float a1 = a[h * 256 + k], a2v = a[h * 256 + 128 + k];
        red[t] = ph * a1 + bb[h * 128 + k] * (a1 + a2v);
        __syncthreads();
        for (int o = 64; o; o >>= 1) {
            if (k < o) red[t] += red[t + o];
            __syncthreads();
        }
        if (k == 0) g_c[h] = red[t];
    }
}

// ---------------- K1b: fold G[j] = W @ Wc_j and bc2 (independent of data) ----
__global__ void __launch_bounds__(256) k_foldG(const float* __restrict__ W,
                                               const float* __restrict__ Wc,
                                               const float* __restrict__ bc,
                                               const float* __restrict__ bb) {
    int j = blockIdx.x, t = threadIdx.x;
    __shared__ float wc[512];
    __shared__ float red[256];
    wc[t] = Wc[(size_t)j * 512 + t];
    wc[t + 256] = Wc[(size_t)j * 512 + 256 + t];
    __syncthreads();
    #pragma unroll
    for (int rep = 0; rep < 4; rep++) {
        int i = rep * 256 + t;                   // (h,d)
        int h = i >> 8;
        const float4* wr = (const float4*)(W + (size_t)i * 128);
        const float4* cw = (const float4*)(wc + h * 128);
        float acc = 0.f;
        #pragma unroll
        for (int q = 0; q < 32; q++) {
            float4 w = wr[q], x = cw[q];
            acc += w.x * x.x + w.y * x.y + w.z * x.z + w.w * x.w;
        }
        g_G[(size_t)j * 1024 + i] = acc;
    }
    // bc2_j = bc_j + b_flat . Wc_j
    float s = bb[t] * wc[t] + bb[t + 256] * wc[t + 256];
    red[t] = s;
    __syncthreads();
    for (int o = 128; o > 16; o >>= 1) {
        if (t < o) red[t] += red[t + o];
        __syncthreads();
    }
    if (t < 32) {
        float v = red[t] + ((t < 16) ? red[t + 16] : 0.f);
        v = (t < 16) ? v : 0.f;
        #pragma unroll
        for (int o = 8; o; o >>= 1) v += __shfl_xor_sync(0xffffffffu, v, o);
        if (t == 0) g_bc2[j] = v + bc[j];
    }
}

// ---------------- K2: fused single-pass, warp-autonomous, f32x2 --------------
__global__ void __launch_bounds__(256, 2) k_fused(const float* __restrict__ code) {
    __shared__ float buf[8][DEPTH * 256];
    __shared__ float cm[8][4], cz[8][4], csc[8][4];

    int t = threadIdx.x, lane = t & 31, w = t >> 5;
    int gw = blockIdx.x * 8 + w;
    int cnt = (N_CODES - gw + NW - 1) / NW;
    auto warp = cg::tiled_partition<32>(cg::this_thread_block());

    float* bw = &buf[w][0];
    const float* base = code + (size_t)gw * 256;

    uint64_t vp[4][4];
    #pragma unroll
    for (int h = 0; h < 4; h++) {
        ulonglong2 va = *(const ulonglong2*)(g_v + h * 256 + lane * 4);
        ulonglong2 vb = *(const ulonglong2*)(g_v + h * 256 + 128 + lane * 4);
        vp[h][0] = va.x; vp[h][1] = va.y; vp[h][2] = vb.x; vp[h][3] = vb.y;
    }
    float c0 = g_c[0], c1 = g_c[1], c2 = g_c[2], c3 = g_c[3];

    float m0 = -1e30f, m1 = -1e30f, m2 = -1e30f, m3 = -1e30f;
    float s0 = 0.f, s1 = 0.f, s2 = 0.f, s3 = 0.f;
    uint64_t acc[4][4];
    #pragma unroll
    for (int h = 0; h < 4; h++)
        #pragma unroll
        for (int k = 0; k < 4; k++) acc[h][k] = 0ull;

    #pragma unroll
    for (int k = 0; k < DEPTH - 1; k++) {
        if (k < cnt) {
            const float* src = base + (size_t)k * NW * 256;
            cp_async16(bw + k * 256 + lane * 4, src + lane * 4);
            cp_async16(bw + k * 256 + 128 + lane * 4, src + 128 + lane * 4);
        }
        cp_commit();
    }

    for (int i = 0; i < cnt; i++) {
        cp_wait<DEPTH - 2>();
        int slot = i % DEPTH;
        ulonglong2 xa = *(const ulonglong2*)(bw + slot * 256 + lane * 4);
        ulonglong2 xb = *(const ulonglong2*)(bw + slot * 256 + 128 + lane * 4);

        int j = i + DEPTH - 1;
        if (j < cnt) {
            const float* src = base + (size_t)j * NW * 256;
            int js = j % DEPTH;
            cp_async16(bw + js * 256 + lane * 4, src + lane * 4);
            cp_async16(bw + js * 256 + 128 + lane * 4, src + 128 + lane * 4);
        }
        cp_commit();

        uint64_t d0 = mul2(vp[0][0], xa.x);
        uint64_t d1 = mul2(vp[1][0], xa.x);
        uint64_t d2 = mul2(vp[2][0], xa.x);
        uint64_t d3 = mul2(vp[3][0], xa.x);
        d0 = fma2(vp[0][1], xa.y, d0); d1 = fma2(vp[1][1], xa.y, d1);
        d2 = fma2(vp[2][1], xa.y, d2); d3 = fma2(vp[3][1], xa.y, d3);
        d0 = fma2(vp[0][2], xb.x, d0); d1 = fma2(vp[1][2], xb.x, d1);
        d2 = fma2(vp[2][2], xb.x, d2); d3 = fma2(vp[3][2], xb.x, d3);
        d0 = fma2(vp[0][3], xb.y, d0); d1 = fma2(vp[1][3], xb.y, d1);
        d2 = fma2(vp[2][3], xb.y, d2); d3 = fma2(vp[3][3], xb.y, d3);
        float2 f0 = unpack2(d0), f1 = unpack2(d1), f2 = unpack2(d2), f3 = unpack2(d3);
        float e0 = f0.x + f0.y, e1 = f1.x + f1.y;
        float e2 = f2.x + f2.y, e3 = f3.x + f3.y;

        e0 = cg::reduce(warp, e0, cg::plus<float>());
        e1 = cg::reduce(warp, e1, cg::plus<float>());
        e2 = cg::reduce(warp, e2, cg::plus<float>());
        e3 = cg::reduce(warp, e3, cg::plus<float>());

        e0 += c0; e1 += c1; e2 += c2; e3 += c3;
        e0 = e0 >= 0.f ? e0 : 0.2f * e0;
        e1 = e1 >= 0.f ? e1 : 0.2f * e1;
        e2 = e2 >= 0.f ? e2 : 0.2f * e2;
        e3 = e3 >= 0.f ? e3 : 0.2f * e3;

        float n0 = fmaxf(m0, e0), n1 = fmaxf(m1, e1);
        float n2 = fmaxf(m2, e2), n3 = fmaxf(m3, e3);
        if (n0 > m0 || n1 > m1 || n2 > m2 || n3 > m3) {
            float r0 = exp2f((m0 - n0) * L2E), r1 = exp2f((m1 - n1) * L2E);
            float r2 = exp2f((m2 - n2) * L2E), r3 = exp2f((m3 - n3) * L2E);
            s0 *= r0; s1 *= r1; s2 *= r2; s3 *= r3;
            uint64_t q0 = pack2(r0), q1 = pack2(r1), q2 = pack2(r2), q3 = pack2(r3);
            #pragma unroll
            for (int k = 0; k < 4; k++) {
                acc[0][k] = mul2(q0, acc[0][k]); acc[1][k] = mul2(q1, acc[1][k]);
                acc[2][k] = mul2(q2, acc[2][k]); acc[3][k] = mul2(q3, acc[3][k]);
            }
            m0 = n0; m1 = n1; m2 = n2; m3 = n3;
        }
        float w0 = exp2f((e0 - m0) * L2E), w1 = exp2f((e1 - m1) * L2E);
        float w2 = exp2f((e2 - m2) * L2E), w3 = exp2f((e3 - m3) * L2E);
        s0 += w0; s1 += w1; s2 += w2; s3 += w3;
        uint64_t p0 = pack2(w0), p1 = pack2(w1), p2 = pack2(w2), p3 = pack2(w3);

        acc[0][0] = fma2(p0, xa.x, acc[0][0]); acc[0][1] = fma2(p0, xa.y, acc[0][1]);
        acc[0][2] = fma2(p0, xb.x, acc[0][2]); acc[0][3] = fma2(p0, xb.y, acc[0][3]);
        acc[1][0] = fma2(p1, xa.x, acc[1][0]); acc[1][1] = fma2(p1, xa.y, acc[1][1]);
        acc[1][2] = fma2(p1, xb.x, acc[1][2]); acc[1][3] = fma2(p1, xb.y, acc[1][3]);
        acc[2][0] = fma2(p2, xa.x, acc[2][0]); acc[2][1] = fma2(p2, xa.y, acc[2][1]);
        acc[2][2] = fma2(p2, xb.x, acc[2][2]); acc[2][3] = fma2(p2, xb.y, acc[2][3]);
        acc[3][0] = fma2(p3, xa.x, acc[3][0]); acc[3][1] = fma2(p3, xa.y, acc[3][1]);
        acc[3][2] = fma2(p3, xb.x, acc[3][2]); acc[3][3] = fma2(p3, xb.y, acc[3][3]);
    }
    cp_wait<0>();

    if (lane == 0) {
        cm[w][0] = m0; cm[w][1] = m1; cm[w][2] = m2; cm[w][3] = m3;
        cz[w][0] = s0; cz[w][1] = s1; cz[w][2] = s2; cz[w][3] = s3;
    }
    __syncthreads();
    if (t < 32) {
        int wp = t >> 2, h = t & 3;
        float mv = cm[wp][h];
        float M = mv;
        M = fmaxf(M, __shfl_xor_sync(0xffffffffu, M, 4));
        M = fmaxf(M, __shfl_xor_sync(0xffffffffu, M, 8));
        M = fmaxf(M, __shfl_xor_sync(0xffffffffu, M, 16));
        float sc = exp2f((mv - M) * L2E);
        csc[wp][h] = sc;
        float z = cz[wp][h] * sc;
        z += __shfl_xor_sync(0xffffffffu, z, 4);
        z += __shfl_xor_sync(0xffffffffu, z, 8);
        z += __shfl_xor_sync(0xffffffffu, z, 16);
        if (t < 4) { g_mb[blockIdx.x * 4 + h] = M; g_zb[blockIdx.x * 4 + h] = z; }
    }
    __syncthreads();
    #pragma unroll
    for (int h = 0; h < 4; h++) {
        float sc = csc[w][h];
        float2 a0 = unpack2(acc[h][0]), a1 = unpack2(acc[h][1]);
        float2 a2 = unpack2(acc[h][2]), a3 = unpack2(acc[h][3]);
        *(float4*)(bw + h * 256 + lane * 4) =
            make_float4(a0.x * sc, a0.y * sc, a1.x * sc, a1.y * sc);
        *(float4*)(bw + h * 256 + 128 + lane * 4) =
            make_float4(a2.x * sc, a2.y * sc, a3.x * sc, a3.y * sc);
    }
    __syncthreads();
    #pragma unroll
    for (int h = 0; h < 4; h++) {
        float v = 0.f;
        #pragma unroll
        for (int w2 = 0; w2 < 8; w2++) v += buf[w2][h * 256 + t];
        g_partB[((size_t)blockIdx.x * 4 + h) * 256 + t] = v;
    }
}

// ---------------- K3: scaled partial reduction (redundant M/Z per block) -----
// block (h = bid&3, q = bid>>2): part2[q,h,d] = sum_{b in quarter} scale[b,h]*partB[b,h,d]
__global__ void __launch_bounds__(256) k_aggsum() {
    int h = blockIdx.x & 3, q = blockIdx.x >> 2, t = threadIdx.x;
    __shared__ float red[256];
    __shared__ float sc[74];

    // block-redundant M
    float lm = -1e30f;
    for (int b = t; b < GRID; b += 256) lm = fmaxf(lm, g_mb[b * 4 + h]);
    red[t] = lm;
    __syncthreads();
    for (int o = 128; o; o >>= 1) {
        if (t < o) red[t] = fmaxf(red[t], red[t + o]);
        __syncthreads();
    }
    float M = red[0];
    __syncthreads();
    // block-redundant Z
    float lz = 0.f;
    for (int b = t; b < GRID; b += 256)
        lz += g_zb[b * 4 + h] * exp2f((g_mb[b * 4 + h] - M) * L2E);
    red[t] = lz;
    __syncthreads();
    for (int o = 128; o; o >>= 1) {
        if (t < o) red[t] += red[t + o];
        __syncthreads();
    }
    float invZ = 1.0f / red[0];
    __syncthreads();

    int b0 = q * 74;
    if (t < 74) sc[t] = exp2f((g_mb[(b0 + t) * 4 + h] - M) * L2E) * invZ;
    __syncthreads();

    float acc = 0.f;
    #pragma unroll 2
    for (int i = 0; i < 74; i++)
        acc = fmaf(g_partB[((size_t)(b0 + i) * 4 + h) * 256 + t], sc[i], acc);
    g_part2[(size_t)blockIdx.x * 256 + t] = acc;
}

// ---------------- K4: final — agg (redundant) -> mho + logits ----------------
// blocks 0..3: mho head h; blocks 4..259: logits j = bid-4
__global__ void __launch_bounds__(256) k_final(const float* __restrict__ W,
                                               const float* __restrict__ bb,
                                               float* __restrict__ out) {
    __shared__ float agg[1024];
    __shared__ float red[256];
    int t = threadIdx.x;
    #pragma unroll
    for (int rep = 0; rep < 4; rep++) {
        int i = rep * 256 + t;                   // (h,d)
        int h = i >> 8, d = i & 255;
        float v = 0.f;
        #pragma unroll
        for (int q = 0; q < 4; q++) v += g_part2[((q * 4 + h) << 8) + d];
        agg[i] = v;
    }
    __syncthreads();

    if (blockIdx.x < 4) {
        int h = blockIdx.x;
        int k = t & 127, half = t >> 7;
        const float* wp = W + (size_t)h * 32768 + (size_t)half * 128 * 128 + k;
        float acc = 0.f;
        #pragma unroll 8
        for (int d = 0; d < 128; d++)
            acc = fmaf(agg[h * 256 + half * 128 + d], wp[(size_t)d * 128], acc);
        red[t] = acc;
        __syncthreads();
        if (t < 128) out[256 + h * 128 + t] = red[t] + red[t + 128] + bb[h * 128 + t];
    } else {
        int j = blockIdx.x - 4;
        const float* Gp = g_G + (size_t)j * 1024;
        float acc = agg[t] * Gp[t] + agg[t + 256] * Gp[t + 256]
                  + agg[t + 512] * Gp[t + 512] + agg[t + 768] * Gp[t + 768];
        red[t] = acc;
        __syncthreads();
        for (int o = 128; o > 16; o >>= 1) {
            if (t < o) red[t] += red[t + o];
            __syncthreads();
        }
        if (t < 32) {
            float v = (t < 16) ? (red[t] + red[t + 16]) : 0.f;
            #pragma unroll
            for (int o = 8; o; o >>= 1) v += __shfl_xor_sync(0xffffffffu, v, o);
            if (t == 0) out[j] = v + g_bc2[j];
        }
    }
}

// ---------------- launch ------------------------------------------------------
extern "C" void kernel_launch(void* const* d_in, const int* in_sizes, int n_in,
                              void* d_out, int out_size) {
    const float* p    = (const float*)d_in[0];
    const float* code = (const float*)d_in[1];
    const float* W    = (const float*)d_in[2];
    const float* bb   = (const float*)d_in[3];
    const float* a    = (const float*)d_in[4];
    const float* Wc   = (const float*)d_in[5];
    const float* bc   = (const float*)d_in[6];
    float* out = (float*)d_out;

    k_prep  <<<3,    512>>>(W, a, p, bb);
    k_foldG <<<256,  256>>>(W, Wc, bc, bb);
    k_fused <<<GRID, 256>>>(code);
    k_aggsum<<<16,   256>>>();
    k_final <<<260,  256>>>(W, bb, out);
}

// round 8
// speedup vs baseline: 1.6656x; 1.6656x over previous
#include <cuda_runtime.h>
#include <cstdint>
#include <cooperative_groups.h>
#include <cooperative_groups/reduce.h>
namespace cg = cooperative_groups;

#define N_CODES 100000
#define CODE_DIM 256
#define HIDDEN 128
#define HEADS 4
#define N_SPEC 256

#define GRID 296               // 2 blocks/SM on 148 SMs: exactly one resident wave
#define NW (GRID * 8)          // 2368 warps, ~42 rows each
#define DEPTH 8                // per-warp cp.async pipeline depth (rows)
#define L2E 1.4426950408889634f

// ---------------- scratch (device globals) ----------------------------------
__device__ __align__(16) float g_v[HEADS * CODE_DIM];   // W[h]@a2[h]
__device__ float g_c[HEADS];
__device__ float g_pm[GRID * HEADS];                    // block max
__device__ float g_pz[GRID * HEADS];                    // block Z
__device__ __align__(16) float g_pacc[HEADS * CODE_DIM * GRID]; // TRANSPOSED [dim][b]
__device__ __align__(16) float g_agg[HEADS * CODE_DIM];
__device__ __align__(16) float g_mho[HEADS * HIDDEN];
__device__ unsigned int g_barctr[4];                    // grid barriers (never reset)

// ---------------- f32x2 helpers ----------------------------------------------
__device__ __forceinline__ uint64_t fma2(uint64_t a, uint64_t b, uint64_t c) {
    uint64_t d;
    asm("fma.rn.f32x2 %0, %1, %2, %3;" : "=l"(d) : "l"(a), "l"(b), "l"(c));
    return d;
}
__device__ __forceinline__ uint64_t mul2(uint64_t a, uint64_t b) {
    uint64_t d;
    asm("mul.rn.f32x2 %0, %1, %2;" : "=l"(d) : "l"(a), "l"(b));
    return d;
}
__device__ __forceinline__ uint64_t pack2(float x) {
    uint64_t d;
    asm("mov.b64 %0, {%1, %1};" : "=l"(d) : "f"(x));
    return d;
}
__device__ __forceinline__ float2 unpack2(uint64_t p) {
    uint32_t lo, hi;
    asm("mov.b64 {%0, %1}, %2;" : "=r"(lo), "=r"(hi) : "l"(p));
    return make_float2(__uint_as_float(lo), __uint_as_float(hi));
}

// ---------------- cp.async helpers ------------------------------------------
__device__ __forceinline__ void cp_async16(void* smem, const void* gmem) {
    uint32_t s = (uint32_t)__cvta_generic_to_shared(smem);
    asm volatile("cp.async.cg.shared.global [%0], [%1], 16;\n" :: "r"(s), "l"(gmem));
}
__device__ __forceinline__ void cp_commit() {
    asm volatile("cp.async.commit_group;\n" ::: "memory");
}
template<int N> __device__ __forceinline__ void cp_wait() {
    asm volatile("cp.async.wait_group %0;\n" :: "n"(N) : "memory");
}

// ---------------- in-kernel grid barrier (generation-safe, deterministic) ----
__device__ __forceinline__ void grid_bar(int id) {
    __syncthreads();
    if (threadIdx.x == 0) {
        __threadfence();
        unsigned int ticket = atomicAdd(&g_barctr[id], 1u);
        unsigned int target = (ticket / GRID + 1u) * GRID;
        while (*((volatile unsigned int*)&g_barctr[id]) < target) {
            __nanosleep(100);
        }
        __threadfence();
    }
    __syncthreads();
}

// ---------------- K1: prep (v projections + score constants) -----------------
__global__ void __launch_bounds__(512) k_prep(const float* __restrict__ W,
                                              const float* __restrict__ a,
                                              const float* __restrict__ p,
                                              const float* __restrict__ bb) {
    int t = threadIdx.x;
    if (blockIdx.x < 2) {
        int idx = blockIdx.x * 512 + t;          // (h,d)
        int h = idx >> 8;
        const float4* wr = (const float4*)(W + (size_t)idx * 128);
        const float4* a2 = (const float4*)(a + h * 256 + 128);
        float av = 0.f;
        #pragma unroll
        for (int q = 0; q < 32; q++) {
            float4 w = wr[q], x = a2[q];
            av += w.x * x.x + w.y * x.y + w.z * x.z + w.w * x.w;
        }
        g_v[idx] = av;
    } else {
        __shared__ float psh[256];
        __shared__ float red[512];
        if (t < 256) psh[t] = p[t];
        __syncthreads();
        int h = t >> 7, k = t & 127;
        const float* wp = W + (size_t)h * 256 * 128 + k;
        float ph = 0.f;
        #pragma unroll 8
        for (int d = 0; d < 256; d++) ph = fmaf(psh[d], wp[(size_t)d * 128], ph);
        float a1 = a[h * 256 + k], a2v = a[h * 256 + 128 + k];
        red[t] = ph * a1 + bb[h * 128 + k] * (a1 + a2v);
        __syncthreads();
        for (int o = 64; o; o >>= 1) {
            if (k < o) red[t] += red[t + o];
            __syncthreads();
        }
        if (k == 0) g_c[h] = red[t];
    }
}

// ---------------- K2: everything else, one persistent kernel -----------------
__global__ void __launch_bounds__(256, 2) k_all(const float* __restrict__ code,
                                                const float* __restrict__ W,
                                                const float* __restrict__ bb,
                                                const float* __restrict__ Wc,
                                                const float* __restrict__ bc,
                                                float* __restrict__ out) {
    __shared__ float buf[8][DEPTH * 256];          // 64 KB, reused by all stages
    __shared__ float cm[8][4], cz[8][4], csc[8][4];
    __shared__ float Msh[4], iZsh[4];

    int t = threadIdx.x, lane = t & 31, w = t >> 5;
    int bid = blockIdx.x;
    int gw = bid * 8 + w;
    int cnt = (N_CODES - gw + NW - 1) / NW;
    auto warp = cg::tiled_partition<32>(cg::this_thread_block());

    float* bw = &buf[w][0];
    const float* base = code + (size_t)gw * 256;

    // ======================= S1: fused streaming pass =======================
    uint64_t vp[4][4];
    #pragma unroll
    for (int h = 0; h < 4; h++) {
        ulonglong2 va = *(const ulonglong2*)(g_v + h * 256 + lane * 4);
        ulonglong2 vb = *(const ulonglong2*)(g_v + h * 256 + 128 + lane * 4);
        vp[h][0] = va.x; vp[h][1] = va.y; vp[h][2] = vb.x; vp[h][3] = vb.y;
    }
    float c0 = g_c[0], c1 = g_c[1], c2 = g_c[2], c3 = g_c[3];

    float m0 = -1e30f, m1 = -1e30f, m2 = -1e30f, m3 = -1e30f;
    float s0 = 0.f, s1 = 0.f, s2 = 0.f, s3 = 0.f;
    uint64_t acc[4][4];
    #pragma unroll
    for (int h = 0; h < 4; h++)
        #pragma unroll
        for (int k = 0; k < 4; k++) acc[h][k] = 0ull;

    #pragma unroll
    for (int k = 0; k < DEPTH - 1; k++) {
        if (k < cnt) {
            const float* src = base + (size_t)k * NW * 256;
            cp_async16(bw + k * 256 + lane * 4, src + lane * 4);
            cp_async16(bw + k * 256 + 128 + lane * 4, src + 128 + lane * 4);
        }
        cp_commit();
    }

    for (int i = 0; i < cnt; i++) {
        cp_wait<DEPTH - 2>();
        int slot = i % DEPTH;
        ulonglong2 xa = *(const ulonglong2*)(bw + slot * 256 + lane * 4);
        ulonglong2 xb = *(const ulonglong2*)(bw + slot * 256 + 128 + lane * 4);

        int j = i + DEPTH - 1;
        if (j < cnt) {
            const float* src = base + (size_t)j * NW * 256;
            int js = j % DEPTH;
            cp_async16(bw + js * 256 + lane * 4, src + lane * 4);
            cp_async16(bw + js * 256 + 128 + lane * 4, src + 128 + lane * 4);
        }
        cp_commit();

        uint64_t d0 = mul2(vp[0][0], xa.x);
        uint64_t d1 = mul2(vp[1][0], xa.x);
        uint64_t d2 = mul2(vp[2][0], xa.x);
        uint64_t d3 = mul2(vp[3][0], xa.x);
        d0 = fma2(vp[0][1], xa.y, d0); d1 = fma2(vp[1][1], xa.y, d1);
        d2 = fma2(vp[2][1], xa.y, d2); d3 = fma2(vp[3][1], xa.y, d3);
        d0 = fma2(vp[0][2], xb.x, d0); d1 = fma2(vp[1][2], xb.x, d1);
        d2 = fma2(vp[2][2], xb.x, d2); d3 = fma2(vp[3][2], xb.x, d3);
        d0 = fma2(vp[0][3], xb.y, d0); d1 = fma2(vp[1][3], xb.y, d1);
        d2 = fma2(vp[2][3], xb.y, d2); d3 = fma2(vp[3][3], xb.y, d3);
        float2 f0 = unpack2(d0), f1 = unpack2(d1), f2 = unpack2(d2), f3 = unpack2(d3);
        float e0 = f0.x + f0.y, e1 = f1.x + f1.y;
        float e2 = f2.x + f2.y, e3 = f3.x + f3.y;

        e0 = cg::reduce(warp, e0, cg::plus<float>());
        e1 = cg::reduce(warp, e1, cg::plus<float>());
        e2 = cg::reduce(warp, e2, cg::plus<float>());
        e3 = cg::reduce(warp, e3, cg::plus<float>());

        e0 += c0; e1 += c1; e2 += c2; e3 += c3;
        e0 = e0 >= 0.f ? e0 : 0.2f * e0;
        e1 = e1 >= 0.f ? e1 : 0.2f * e1;
        e2 = e2 >= 0.f ? e2 : 0.2f * e2;
        e3 = e3 >= 0.f ? e3 : 0.2f * e3;

        float n0 = fmaxf(m0, e0), n1 = fmaxf(m1, e1);
        float n2 = fmaxf(m2, e2), n3 = fmaxf(m3, e3);
        if (n0 > m0 || n1 > m1 || n2 > m2 || n3 > m3) {
            float r0 = exp2f((m0 - n0) * L2E), r1 = exp2f((m1 - n1) * L2E);
            float r2 = exp2f((m2 - n2) * L2E), r3 = exp2f((m3 - n3) * L2E);
            s0 *= r0; s1 *= r1; s2 *= r2; s3 *= r3;
            uint64_t q0 = pack2(r0), q1 = pack2(r1), q2 = pack2(r2), q3 = pack2(r3);
            #pragma unroll
            for (int k = 0; k < 4; k++) {
                acc[0][k] = mul2(q0, acc[0][k]); acc[1][k] = mul2(q1, acc[1][k]);
                acc[2][k] = mul2(q2, acc[2][k]); acc[3][k] = mul2(q3, acc[3][k]);
            }
            m0 = n0; m1 = n1; m2 = n2; m3 = n3;
        }
        float w0 = exp2f((e0 - m0) * L2E), w1 = exp2f((e1 - m1) * L2E);
        float w2 = exp2f((e2 - m2) * L2E), w3 = exp2f((e3 - m3) * L2E);
        s0 += w0; s1 += w1; s2 += w2; s3 += w3;
        uint64_t p0 = pack2(w0), p1 = pack2(w1), p2 = pack2(w2), p3 = pack2(w3);

        acc[0][0] = fma2(p0, xa.x, acc[0][0]); acc[0][1] = fma2(p0, xa.y, acc[0][1]);
        acc[0][2] = fma2(p0, xb.x, acc[0][2]); acc[0][3] = fma2(p0, xb.y, acc[0][3]);
        acc[1][0] = fma2(p1, xa.x, acc[1][0]); acc[1][1] = fma2(p1, xa.y, acc[1][1]);
        acc[1][2] = fma2(p1, xb.x, acc[1][2]); acc[1][3] = fma2(p1, xb.y, acc[1][3]);
        acc[2][0] = fma2(p2, xa.x, acc[2][0]); acc[2][1] = fma2(p2, xa.y, acc[2][1]);
        acc[2][2] = fma2(p2, xb.x, acc[2][2]); acc[2][3] = fma2(p2, xb.y, acc[2][3]);
        acc[3][0] = fma2(p3, xa.x, acc[3][0]); acc[3][1] = fma2(p3, xa.y, acc[3][1]);
        acc[3][2] = fma2(p3, xb.x, acc[3][2]); acc[3][3] = fma2(p3, xb.y, acc[3][3]);
    }
    cp_wait<0>();

    // per-block combine across 8 warps
    if (lane == 0) {
        cm[w][0] = m0; cm[w][1] = m1; cm[w][2] = m2; cm[w][3] = m3;
        cz[w][0] = s0; cz[w][1] = s1; cz[w][2] = s2; cz[w][3] = s3;
    }
    __syncthreads();
    if (t < 32) {
        int wp2 = t >> 2, h = t & 3;
        float mv = cm[wp2][h];
        float M = mv;
        M = fmaxf(M, __shfl_xor_sync(0xffffffffu, M, 4));
        M = fmaxf(M, __shfl_xor_sync(0xffffffffu, M, 8));
        M = fmaxf(M, __shfl_xor_sync(0xffffffffu, M, 16));
        float sc = exp2f((mv - M) * L2E);
        csc[wp2][h] = sc;
        float z = cz[wp2][h] * sc;
        z += __shfl_xor_sync(0xffffffffu, z, 4);
        z += __shfl_xor_sync(0xffffffffu, z, 8);
        z += __shfl_xor_sync(0xffffffffu, z, 16);
        if (t < 4) { g_pm[bid * 4 + h] = M; g_pz[bid * 4 + h] = z; }
    }
    __syncthreads();
    #pragma unroll
    for (int h = 0; h < 4; h++) {
        float sc = csc[w][h];
        float2 a0 = unpack2(acc[h][0]), a1 = unpack2(acc[h][1]);
        float2 a2 = unpack2(acc[h][2]), a3 = unpack2(acc[h][3]);
        *(float4*)(bw + h * 256 + lane * 4) =
            make_float4(a0.x * sc, a0.y * sc, a1.x * sc, a1.y * sc);
        *(float4*)(bw + h * 256 + 128 + lane * 4) =
            make_float4(a2.x * sc, a2.y * sc, a3.x * sc, a3.y * sc);
    }
    __syncthreads();
    #pragma unroll
    for (int h = 0; h < 4; h++) {
        float v = 0.f;
        #pragma unroll
        for (int w2 = 0; w2 < 8; w2++) v += buf[w2][h * 256 + t];
        g_pacc[(size_t)(h * 256 + t) * GRID + bid] = v;   // transposed [dim][b]
    }

    grid_bar(0);

    // ======================= S2: M/Z (redundant) + agg =======================
    float* scratch = &buf[0][0];                  // reuse 64 KB smem
    // stage m and z into smem (coalesced L2 reads)
    for (int i = t; i < GRID * 4; i += 256) {
        scratch[i] = g_pm[i];
        scratch[GRID * 4 + i] = g_pz[i];
    }
    __syncthreads();
    if (w < 4) {                                   // warp w handles head w
        float M = -1e30f;
        for (int b2 = lane; b2 < GRID; b2 += 32) M = fmaxf(M, scratch[b2 * 4 + w]);
        M = cg::reduce(warp, M, cg::greater<float>());
        float Z = 0.f;
        for (int b2 = lane; b2 < GRID; b2 += 32)
            Z += scratch[GRID * 4 + b2 * 4 + w] * exp2f((scratch[b2 * 4 + w] - M) * L2E);
        Z = cg::reduce(warp, Z, cg::plus<float>());
        if (lane == 0) { Msh[w] = M; iZsh[w] = 1.0f / Z; }
    }
    __syncthreads();
    // folded scales
    for (int i = t; i < GRID * 4; i += 256) {
        int h = i & 3;
        scratch[2 * GRID * 4 + i] = exp2f((scratch[i] - Msh[h]) * L2E) * iZsh[h];
    }
    __syncthreads();
    if (bid < 256) {
        float* red = scratch + 3 * GRID * 4 + 32;  // 256-float reduce area
        #pragma unroll
        for (int q = 0; q < 4; q++) {
            int dim = bid * 4 + q;
            int h = dim >> 8;
            float p2 = 0.f;
            for (int b2 = t; b2 < GRID; b2 += 256)
                p2 = fmaf(g_pacc[(size_t)dim * GRID + b2],
                          scratch[2 * GRID * 4 + b2 * 4 + h], p2);
            red[t] = p2;
            __syncthreads();
            for (int o = 128; o; o >>= 1) {
                if (t < o) red[t] += red[t + o];
                __syncthreads();
            }
            if (t == 0) g_agg[dim] = red[0];
            __syncthreads();
        }
    }

    grid_bar(1);

    // ======================= S3: mho (blocks 0..3) ==========================
    if (bid < 4) {
        int h = bid;
        float* agg_sh = &buf[0][0];
        float* red = &buf[0][0] + 512;
        if (t < 256) agg_sh[t] = g_agg[h * 256 + t];
        __syncthreads();
        int k = t & 127, half = t >> 7;
        const float* wp = W + (size_t)h * 32768 + (size_t)half * 128 * 128 + k;
        float a2 = 0.f;
        #pragma unroll 8
        for (int d = 0; d < 128; d++)
            a2 = fmaf(agg_sh[half * 128 + d], wp[(size_t)d * 128], a2);
        red[t] = a2;
        __syncthreads();
        if (t < 128) {
            float v = red[t] + red[t + 128] + bb[h * 128 + t];
            g_mho[h * 128 + t] = v;
            out[256 + h * 128 + t] = v;
        }
    }

    grid_bar(2);

    // ======================= S4: logits (blocks 4..259) =====================
    if (bid >= 4 && bid < 260) {
        int j = bid - 4;
        float* mho_sh = &buf[0][0];
        float* red = &buf[0][0] + 1024;
        mho_sh[t] = g_mho[t];
        mho_sh[t + 256] = g_mho[t + 256];
        __syncthreads();
        const float* wc = Wc + (size_t)j * 512;
        float v = wc[t] * mho_sh[t] + wc[t + 256] * mho_sh[t + 256];
        red[t] = v;
        __syncthreads();
        for (int o = 128; o > 16; o >>= 1) {
            if (t < o) red[t] += red[t + o];
            __syncthreads();
        }
        if (t < 32) {
            float s = (t < 16) ? (red[t] + red[t + 16]) : 0.f;
            #pragma unroll
            for (int o = 8; o; o >>= 1) s += __shfl_xor_sync(0xffffffffu, s, o);
            if (t == 0) out[j] = s + bc[j];
        }
    }
}

// ---------------- launch ------------------------------------------------------
extern "C" void kernel_launch(void* const* d_in, const int* in_sizes, int n_in,
                              void* d_out, int out_size) {
    const float* p    = (const float*)d_in[0];
    const float* code = (const float*)d_in[1];
    const float* W    = (const float*)d_in[2];
    const float* bb   = (const float*)d_in[3];
    const float* a    = (const float*)d_in[4];
    const float* Wc   = (const float*)d_in[5];
    const float* bc   = (const float*)d_in[6];
    float* out = (float*)d_out;

    k_prep<<<3,    512>>>(W, a, p, bb);
    k_all <<<GRID, 256>>>(code, W, bb, Wc, bc, out);
}